// round 9
// baseline (speedup 1.0000x reference)
#include <cuda_runtime.h>
#include <cuda_bf16.h>
#include <math.h>

#define N_NODES 20000
#define N_EDGES 320000
#define EMB 256

// ---------------- scratch: plain ld/st only ----------------
__device__ float g_bufA[N_NODES * EMB];
__device__ float g_bufB[N_NODES * EMB];
__device__ float g_dinv[N_NODES];

#define SEL_EXT  0
#define SEL_BUFA 1
#define SEL_BUFB 2

template<int SEL>
__device__ __forceinline__ const float* pick_src(const float* ext) {
    if (SEL == SEL_BUFA) return (const float*)g_bufA;
    if (SEL == SEL_BUFB) return (const float*)g_bufB;
    return ext;
}
template<int SEL>
__device__ __forceinline__ float* pick_dst(float* ext) {
    if (SEL == SEL_BUFA) return g_bufA;
    if (SEL == SEL_BUFB) return g_bufB;
    return ext;
}

// ---------------- degree / normalization (scratch = d_out) ----------------
__global__ void k_deg_init(float* __restrict__ scratch) {
    int i = blockIdx.x * blockDim.x + threadIdx.x;
    if (i < N_NODES) scratch[i] = 1.0f;   // self-loop
}

__global__ void k_deg_edges(const int* __restrict__ dst, float* __restrict__ scratch) {
    int e = blockIdx.x * blockDim.x + threadIdx.x;
    if (e < N_EDGES) atomicAdd(&scratch[dst[e]], 1.0f);
}

__global__ void k_dinv(const float* __restrict__ scratch) {
    int i = blockIdx.x * blockDim.x + threadIdx.x;
    if (i < N_NODES) g_dinv[i] = rsqrtf(scratch[i]);
}

// ---------------- SGEMM: C[M,N] = A[M,K] @ W[K,N] (+bias)(+relu) ----------------
// 128x128 tile, BK=8, 8x8 per thread, 256 threads, float4 loads.
template<int ASEL, int CSEL, bool BIAS, bool RELU>
__global__ __launch_bounds__(256) void sgemm128(
    const float* __restrict__ Aext, const float* __restrict__ W,
    const float* __restrict__ bias, float* __restrict__ Cext,
    int M, int N, int K)
{
    const float* A = pick_src<ASEL>(Aext);
    float* C = pick_dst<CSEL>(Cext);

    __shared__ float As[8][128];
    __shared__ float Bs[8][128];

    const int tid = threadIdx.x;
    const int rowBase = blockIdx.y * 128;
    const int colBase = blockIdx.x * 128;

    const int tRow = (tid / 16) * 8;
    const int tCol = (tid % 16) * 8;

    float acc[8][8];
    #pragma unroll
    for (int i = 0; i < 8; i++)
        #pragma unroll
        for (int j = 0; j < 8; j++) acc[i][j] = 0.0f;

    const int aRow = tid >> 1;          // 0..127
    const int aSeg = (tid & 1) * 4;     // 0 or 4
    const int bRow = tid >> 5;          // 0..7
    const int bCol = (tid & 31) * 4;    // 0..124

    for (int k0 = 0; k0 < K; k0 += 8) {
        // A tile: 128 rows x 8 k, stored transposed As[k][row]
        float4 av = make_float4(0.f, 0.f, 0.f, 0.f);
        int gRow = rowBase + aRow;
        int gkA = k0 + aSeg;
        if (gRow < M && gkA < K) {
            if (gkA + 3 < K) {
                av = *reinterpret_cast<const float4*>(&A[(size_t)gRow * K + gkA]);
            } else {
                float t[4] = {0.f, 0.f, 0.f, 0.f};
                for (int i = 0; i < 4; i++)
                    if (gkA + i < K) t[i] = A[(size_t)gRow * K + gkA + i];
                av = make_float4(t[0], t[1], t[2], t[3]);
            }
        }
        As[aSeg + 0][aRow] = av.x;
        As[aSeg + 1][aRow] = av.y;
        As[aSeg + 2][aRow] = av.z;
        As[aSeg + 3][aRow] = av.w;

        // W tile: 8 k-rows x 128 cols
        float4 bv = make_float4(0.f, 0.f, 0.f, 0.f);
        int gkB = k0 + bRow;
        if (gkB < K)
            bv = *reinterpret_cast<const float4*>(&W[(size_t)gkB * N + colBase + bCol]);
        *reinterpret_cast<float4*>(&Bs[bRow][bCol]) = bv;

        __syncthreads();

        #pragma unroll
        for (int kk = 0; kk < 8; kk++) {
            float ra[8], rb[8];
            #pragma unroll
            for (int i = 0; i < 8; i += 4) {
                float4 v = *reinterpret_cast<const float4*>(&As[kk][tRow + i]);
                ra[i] = v.x; ra[i+1] = v.y; ra[i+2] = v.z; ra[i+3] = v.w;
            }
            #pragma unroll
            for (int j = 0; j < 8; j += 4) {
                float4 v = *reinterpret_cast<const float4*>(&Bs[kk][tCol + j]);
                rb[j] = v.x; rb[j+1] = v.y; rb[j+2] = v.z; rb[j+3] = v.w;
            }
            #pragma unroll
            for (int i = 0; i < 8; i++)
                #pragma unroll
                for (int j = 0; j < 8; j++)
                    acc[i][j] = fmaf(ra[i], rb[j], acc[i][j]);
        }
        __syncthreads();
    }

    #pragma unroll
    for (int i = 0; i < 8; i++) {
        int gRow = rowBase + tRow + i;
        if (gRow >= M) continue;
        #pragma unroll
        for (int j = 0; j < 8; j += 4) {
            float4 v = make_float4(acc[i][j], acc[i][j+1], acc[i][j+2], acc[i][j+3]);
            int gCol = colBase + tCol + j;
            if (BIAS) {
                v.x += bias[gCol + 0];
                v.y += bias[gCol + 1];
                v.z += bias[gCol + 2];
                v.w += bias[gCol + 3];
            }
            if (RELU) {
                v.x = fmaxf(v.x, 0.f); v.y = fmaxf(v.y, 0.f);
                v.z = fmaxf(v.z, 0.f); v.w = fmaxf(v.w, 0.f);
            }
            *reinterpret_cast<float4*>(&C[(size_t)gRow * N + gCol]) = v;
        }
    }
}

// ---------------- aggregation: reads g_bufA, writes `out` (harness memory) -------
// out[i,:] = bufA[i,:] * dinv[i]^2 + bias
__global__ void k_agg_init(const float* __restrict__ bias, float* __restrict__ out) {
    int idx = blockIdx.x * blockDim.x + threadIdx.x;
    if (idx >= N_NODES * EMB) return;
    int i = idx >> 8;
    int c = idx & 255;
    float di = g_dinv[i];
    out[idx] = g_bufA[idx] * di * di + bias[c];
}

// out[dst,:] += bufA[src,:] * dinv[src]*dinv[dst]
__global__ void k_agg_edges(const int* __restrict__ src,
                            const int* __restrict__ dst,
                            float* __restrict__ out) {
    long long idx = (long long)blockIdx.x * blockDim.x + threadIdx.x;
    if (idx >= (long long)N_EDGES * EMB) return;
    int e = (int)(idx >> 8);
    int c = (int)(idx & 255);
    int s = src[e];
    int d = dst[e];
    float nrm = g_dinv[s] * g_dinv[d];
    atomicAdd(&out[(size_t)d * EMB + c], g_bufA[(size_t)s * EMB + c] * nrm);
}

__global__ void k_relu(float* __restrict__ x) {
    int idx = blockIdx.x * blockDim.x + threadIdx.x;
    if (idx < N_NODES * EMB) x[idx] = fmaxf(x[idx], 0.0f);
}

// ---------------- launch ----------------
extern "C" void kernel_launch(void* const* d_in, const int* in_sizes, int n_in,
                              void* d_out, int out_size) {
    const float* x       = (const float*)d_in[0];
    const int*   ei      = (const int*)d_in[1];     // [2, E] int32 (JAX x64 disabled)
    const float* conv0_w = (const float*)d_in[2];
    const float* conv0_b = (const float*)d_in[3];
    const float* conv1_w = (const float*)d_in[4];
    const float* conv1_b = (const float*)d_in[5];
    const float* conv2_w = (const float*)d_in[6];
    const float* conv2_b = (const float*)d_in[7];
    const float* mlp1_w  = (const float*)d_in[8];
    const float* mlp1_b  = (const float*)d_in[9];
    const float* mlp2_w  = (const float*)d_in[10];
    const float* mlp2_b  = (const float*)d_in[11];
    const float* mlp3_w  = (const float*)d_in[12];
    const float* mlp3_b  = (const float*)d_in[13];
    float* out = (float*)d_out;

    const int* src = ei;
    const int* dst = ei + N_EDGES;

    // degree + normalization (scratch in d_out; overwritten by agg later)
    k_deg_init<<<(N_NODES + 255) / 256, 256>>>(out);
    k_deg_edges<<<(N_EDGES + 255) / 256, 256>>>(dst, out);
    k_dinv<<<(N_NODES + 255) / 256, 256>>>(out);

    dim3 gblk(256);
    dim3 ggrid(EMB / 128, (N_NODES + 127) / 128);   // (2, 157)
    const int nodeElems = N_NODES * EMB;
    const int nodeBlocks = (nodeElems + 255) / 256;
    const long long edgeElems = (long long)N_EDGES * EMB;
    const int edgeBlocks = (int)((edgeElems + 255) / 256);

    // conv0: bufA = x @ W0 ; out = agg(bufA)+b0 ; relu(out)
    sgemm128<SEL_EXT, SEL_BUFA, false, false><<<ggrid, gblk>>>(x, conv0_w, conv0_b, out, N_NODES, EMB, 300);
    k_agg_init<<<nodeBlocks, 256>>>(conv0_b, out);
    k_agg_edges<<<edgeBlocks, 256>>>(src, dst, out);
    k_relu<<<nodeBlocks, 256>>>(out);

    // conv1: bufA = out @ W1 ; out = agg(bufA)+b1 ; relu(out)
    sgemm128<SEL_EXT, SEL_BUFA, false, false><<<ggrid, gblk>>>(out, conv1_w, conv1_b, out, N_NODES, EMB, EMB);
    k_agg_init<<<nodeBlocks, 256>>>(conv1_b, out);
    k_agg_edges<<<edgeBlocks, 256>>>(src, dst, out);
    k_relu<<<nodeBlocks, 256>>>(out);

    // conv2 (no relu): bufA = out @ W2 ; out = agg(bufA)+b2
    sgemm128<SEL_EXT, SEL_BUFA, false, false><<<ggrid, gblk>>>(out, conv2_w, conv2_b, out, N_NODES, EMB, EMB);
    k_agg_init<<<nodeBlocks, 256>>>(conv2_b, out);
    k_agg_edges<<<edgeBlocks, 256>>>(src, dst, out);

    // MLP: out -> bufA -> bufB -> out
    sgemm128<SEL_EXT,  SEL_BUFA, true, true ><<<ggrid, gblk>>>(out, mlp1_w, mlp1_b, out, N_NODES, EMB, EMB);
    sgemm128<SEL_BUFA, SEL_BUFB, true, true ><<<ggrid, gblk>>>(x,   mlp2_w, mlp2_b, out, N_NODES, EMB, EMB);
    sgemm128<SEL_BUFB, SEL_EXT,  true, false><<<ggrid, gblk>>>(x,   mlp3_w, mlp3_b, out, N_NODES, EMB, EMB);
}

// round 10
// speedup vs baseline: 2.3197x; 2.3197x over previous
#include <cuda_runtime.h>
#include <cuda_bf16.h>
#include <mma.h>
#include <math.h>

using namespace nvcuda;

#define N_NODES 20000
#define N_EDGES 320000
#define EMB 256

// ---------------- device-global scratch (no host-side address use) ---------------
__device__ float g_bufA[N_NODES * EMB];
__device__ float g_bufB[N_NODES * EMB];
__device__ float g_dinv[N_NODES];
__device__ int   g_cnt[N_NODES];
__device__ int   g_rowstart[N_NODES + 1];
__device__ int   g_cursor[N_NODES];
__device__ int   g_esrc[N_EDGES];
__device__ float g_enrm[N_EDGES];

#define SEL_EXT  0
#define SEL_BUFA 1
#define SEL_BUFB 2

template<int SEL>
__device__ __forceinline__ const float* pick_src(const float* ext) {
    if (SEL == SEL_BUFA) return (const float*)g_bufA;
    if (SEL == SEL_BUFB) return (const float*)g_bufB;
    return ext;
}
template<int SEL>
__device__ __forceinline__ float* pick_dst(float* ext) {
    if (SEL == SEL_BUFA) return g_bufA;
    if (SEL == SEL_BUFB) return g_bufB;
    return ext;
}

// ---------------- CSR build ----------------
__global__ void k_zero_cnt() {
    int i = blockIdx.x * blockDim.x + threadIdx.x;
    if (i < N_NODES) g_cnt[i] = 0;
}
__global__ void k_hist(const int* __restrict__ dst) {
    int e = blockIdx.x * blockDim.x + threadIdx.x;
    if (e < N_EDGES) atomicAdd(&g_cnt[dst[e]], 1);
}
__global__ void k_dinv_k() {
    int i = blockIdx.x * blockDim.x + threadIdx.x;
    if (i < N_NODES) g_dinv[i] = rsqrtf(1.0f + (float)g_cnt[i]);
}
// single-block exclusive scan over g_cnt -> g_rowstart, g_cursor
__global__ void k_scan() {
    __shared__ int part[1024];
    const int CH = 20;                  // 1024*20 = 20480 >= 20000
    int t = threadIdx.x;
    int base = t * CH;
    int loc[CH];
    int s = 0;
    #pragma unroll
    for (int u = 0; u < CH; u++) {
        int idx = base + u;
        int v = (idx < N_NODES) ? g_cnt[idx] : 0;
        loc[u] = s;
        s += v;
    }
    part[t] = s;
    __syncthreads();
    for (int off = 1; off < 1024; off <<= 1) {
        int v = (t >= off) ? part[t - off] : 0;
        __syncthreads();
        part[t] += v;
        __syncthreads();
    }
    int pre = (t == 0) ? 0 : part[t - 1];
    #pragma unroll
    for (int u = 0; u < CH; u++) {
        int idx = base + u;
        if (idx < N_NODES) {
            g_rowstart[idx] = pre + loc[u];
            g_cursor[idx]   = pre + loc[u];
        }
    }
    if (t == 1023) g_rowstart[N_NODES] = part[1023];
}
__global__ void k_fill(const int* __restrict__ src, const int* __restrict__ dst) {
    int e = blockIdx.x * blockDim.x + threadIdx.x;
    if (e >= N_EDGES) return;
    int s = src[e], d = dst[e];
    int pos = atomicAdd(&g_cursor[d], 1);
    g_esrc[pos] = s;
    g_enrm[pos] = g_dinv[s] * g_dinv[d];
}

// ---------------- bf16-split tensor-core GEMM ----------------
// C[M,256] = A[M,K] @ W[K,256] (+bias)(+relu).  Split a=hi+lo, w=hi+lo;
// acc += hi*hi + hi*lo + lo*hi  (fp32 accumulate) -> ~1e-5 rel error.
// Block tile 128x128, BK=16, 8 warps (2m x 4n), warp tile 64x32.
template<int ASEL, int CSEL, bool BIAS, bool RELU>
__global__ __launch_bounds__(256) void gemm_bf16s(
    const float* __restrict__ Aext, const float* __restrict__ W,
    const float* __restrict__ bias, float* __restrict__ Cext,
    int M, int K)
{
    const float* A = pick_src<ASEL>(Aext);
    float* C = pick_dst<CSEL>(Cext);
    const int N = EMB;

    __shared__ __nv_bfloat16 As_hi[128][16];
    __shared__ __nv_bfloat16 As_lo[128][16];
    __shared__ __nv_bfloat16 Ws_hi[16][128];
    __shared__ __nv_bfloat16 Ws_lo[16][128];
    __shared__ float stage[8][16][20];

    const int tid  = threadIdx.x;
    const int warp = tid >> 5;
    const int lane = tid & 31;
    const int warpM = warp >> 2;        // 0..1
    const int warpN = warp & 3;         // 0..3
    const int rowBase = blockIdx.y * 128;
    const int colBase = blockIdx.x * 128;

    wmma::fragment<wmma::accumulator, 16, 16, 16, float> acc[4][2];
    #pragma unroll
    for (int i = 0; i < 4; i++)
        #pragma unroll
        for (int j = 0; j < 2; j++) wmma::fill_fragment(acc[i][j], 0.0f);

    for (int k0 = 0; k0 < K; k0 += 16) {
        // ---- load A slab: 128 rows x 16 k (float4, guarded), split to bf16 hi/lo
        #pragma unroll
        for (int it = 0; it < 2; it++) {
            int r = (tid >> 2) + it * 64;
            int seg = (tid & 3) * 4;
            int gRow = rowBase + r;
            int gk = k0 + seg;
            float4 v = make_float4(0.f, 0.f, 0.f, 0.f);
            if (gRow < M) {
                if (gk + 3 < K) {
                    v = *reinterpret_cast<const float4*>(&A[(size_t)gRow * K + gk]);
                } else {
                    float t[4] = {0.f, 0.f, 0.f, 0.f};
                    for (int u = 0; u < 4; u++)
                        if (gk + u < K) t[u] = A[(size_t)gRow * K + gk + u];
                    v = make_float4(t[0], t[1], t[2], t[3]);
                }
            }
            float vv[4] = {v.x, v.y, v.z, v.w};
            #pragma unroll
            for (int u = 0; u < 4; u++) {
                __nv_bfloat16 h = __float2bfloat16(vv[u]);
                As_hi[r][seg + u] = h;
                As_lo[r][seg + u] = __float2bfloat16(vv[u] - __bfloat162float(h));
            }
        }
        // ---- load W slab: 16 k-rows x 128 cols
        {
            int kr = tid >> 4;              // 0..15
            int c4 = (tid & 15);            // float4 index 0..15
            int gk = k0 + kr;
            #pragma unroll
            for (int it = 0; it < 2; it++) {
                int c = (c4 + it * 16) * 4; // 0..124
                float4 v = make_float4(0.f, 0.f, 0.f, 0.f);
                if (gk < K)
                    v = *reinterpret_cast<const float4*>(&W[(size_t)gk * N + colBase + c]);
                float vv[4] = {v.x, v.y, v.z, v.w};
                #pragma unroll
                for (int u = 0; u < 4; u++) {
                    __nv_bfloat16 h = __float2bfloat16(vv[u]);
                    Ws_hi[kr][c + u] = h;
                    Ws_lo[kr][c + u] = __float2bfloat16(vv[u] - __bfloat162float(h));
                }
            }
        }
        __syncthreads();

        // ---- mma
        wmma::fragment<wmma::matrix_a, 16, 16, 16, __nv_bfloat16, wmma::row_major> a_hi[4], a_lo[4];
        wmma::fragment<wmma::matrix_b, 16, 16, 16, __nv_bfloat16, wmma::row_major> b_hi[2], b_lo[2];
        #pragma unroll
        for (int i = 0; i < 4; i++) {
            int m = warpM * 64 + i * 16;
            wmma::load_matrix_sync(a_hi[i], &As_hi[m][0], 16);
            wmma::load_matrix_sync(a_lo[i], &As_lo[m][0], 16);
        }
        #pragma unroll
        for (int j = 0; j < 2; j++) {
            int n = warpN * 32 + j * 16;
            wmma::load_matrix_sync(b_hi[j], &Ws_hi[0][n], 128);
            wmma::load_matrix_sync(b_lo[j], &Ws_lo[0][n], 128);
        }
        #pragma unroll
        for (int i = 0; i < 4; i++)
            #pragma unroll
            for (int j = 0; j < 2; j++) {
                wmma::mma_sync(acc[i][j], a_hi[i], b_hi[j], acc[i][j]);
                wmma::mma_sync(acc[i][j], a_hi[i], b_lo[j], acc[i][j]);
                wmma::mma_sync(acc[i][j], a_lo[i], b_hi[j], acc[i][j]);
            }
        __syncthreads();
    }

    // ---- epilogue: stage each 16x16 frag in smem, guarded global writes
    #pragma unroll
    for (int i = 0; i < 4; i++) {
        #pragma unroll
        for (int j = 0; j < 2; j++) {
            wmma::store_matrix_sync(&stage[warp][0][0], acc[i][j], 20, wmma::mem_row_major);
            __syncwarp();
            int r = lane >> 1;
            int cs = (lane & 1) * 8;
            int gRow = rowBase + warpM * 64 + i * 16 + r;
            int gColBase = colBase + warpN * 32 + j * 16 + cs;
            if (gRow < M) {
                #pragma unroll
                for (int u = 0; u < 8; u++) {
                    float v = stage[warp][r][cs + u];
                    int gCol = gColBase + u;
                    if (BIAS) v += bias[gCol];
                    if (RELU) v = fmaxf(v, 0.0f);
                    C[(size_t)gRow * EMB + gCol] = v;
                }
            }
            __syncwarp();
        }
    }
}

// ---------------- fused CSR aggregation: dst = self + bias + sum(neigh) (+relu) --
// reads g_bufA, block per node, thread per channel.
template<int DSEL, bool RELU>
__global__ void k_agg_csr(const float* __restrict__ bias, float* __restrict__ Dext) {
    float* D = pick_dst<DSEL>(Dext);
    int d = blockIdx.x;
    int c = threadIdx.x;
    float di = g_dinv[d];
    float acc = g_bufA[(size_t)d * EMB + c] * di * di + bias[c];
    int b0 = g_rowstart[d];
    int b1 = g_rowstart[d + 1];
    for (int j = b0; j < b1; j++) {
        int s = g_esrc[j];
        acc += g_bufA[(size_t)s * EMB + c] * g_enrm[j];
    }
    if (RELU) acc = fmaxf(acc, 0.0f);
    D[(size_t)d * EMB + c] = acc;
}

// ---------------- launch ----------------
extern "C" void kernel_launch(void* const* d_in, const int* in_sizes, int n_in,
                              void* d_out, int out_size) {
    const float* x       = (const float*)d_in[0];
    const int*   ei      = (const int*)d_in[1];     // [2, E] int32
    const float* conv0_w = (const float*)d_in[2];
    const float* conv0_b = (const float*)d_in[3];
    const float* conv1_w = (const float*)d_in[4];
    const float* conv1_b = (const float*)d_in[5];
    const float* conv2_w = (const float*)d_in[6];
    const float* conv2_b = (const float*)d_in[7];
    const float* mlp1_w  = (const float*)d_in[8];
    const float* mlp1_b  = (const float*)d_in[9];
    const float* mlp2_w  = (const float*)d_in[10];
    const float* mlp2_b  = (const float*)d_in[11];
    const float* mlp3_w  = (const float*)d_in[12];
    const float* mlp3_b  = (const float*)d_in[13];
    float* out = (float*)d_out;

    const int* src = ei;
    const int* dst = ei + N_EDGES;

    // CSR build + norms
    k_zero_cnt<<<(N_NODES + 255) / 256, 256>>>();
    k_hist<<<(N_EDGES + 255) / 256, 256>>>(dst);
    k_dinv_k<<<(N_NODES + 255) / 256, 256>>>();
    k_scan<<<1, 1024>>>();
    k_fill<<<(N_EDGES + 255) / 256, 256>>>(src, dst);

    dim3 gblk(256);
    dim3 ggrid(2, (N_NODES + 127) / 128);   // 128-col x 128-row tiles over [20000,256]

    // conv0: bufA = x @ W0 ; bufB = agg(bufA)+b0, relu
    gemm_bf16s<SEL_EXT,  SEL_BUFA, false, false><<<ggrid, gblk>>>(x, conv0_w, conv0_b, out, N_NODES, 300);
    k_agg_csr<SEL_BUFB, true ><<<N_NODES, EMB>>>(conv0_b, out);

    // conv1
    gemm_bf16s<SEL_BUFB, SEL_BUFA, false, false><<<ggrid, gblk>>>(x, conv1_w, conv1_b, out, N_NODES, EMB);
    k_agg_csr<SEL_BUFB, true ><<<N_NODES, EMB>>>(conv1_b, out);

    // conv2 (no relu)
    gemm_bf16s<SEL_BUFB, SEL_BUFA, false, false><<<ggrid, gblk>>>(x, conv2_w, conv2_b, out, N_NODES, EMB);
    k_agg_csr<SEL_BUFB, false><<<N_NODES, EMB>>>(conv2_b, out);

    // MLP: bufB -> bufA -> bufB -> out
    gemm_bf16s<SEL_BUFB, SEL_BUFA, true, true ><<<ggrid, gblk>>>(x, mlp1_w, mlp1_b, out, N_NODES, EMB);
    gemm_bf16s<SEL_BUFA, SEL_BUFB, true, true ><<<ggrid, gblk>>>(x, mlp2_w, mlp2_b, out, N_NODES, EMB);
    gemm_bf16s<SEL_BUFB, SEL_EXT,  true, false><<<ggrid, gblk>>>(x, mlp3_w, mlp3_b, out, N_NODES, EMB);
}

// round 11
// speedup vs baseline: 3.3255x; 1.4336x over previous
#include <cuda_runtime.h>
#include <cuda_bf16.h>
#include <mma.h>
#include <math.h>

using namespace nvcuda;

#define N_NODES 20000
#define N_EDGES 320000
#define EMB 256
#define KPAD0 320              // conv0 K=300 padded; others use 256
#define MROWS 20096            // 157*128 rows allocated (OOB-read safe)
#define ASZ (MROWS * KPAD0)

// ---------------- device-global scratch ----------------
__device__ float g_bufA[N_NODES * EMB];          // conv GEMM float output
__device__ float g_dinv[N_NODES];
__device__ int   g_cnt[N_NODES];
__device__ int   g_rowstart[N_NODES];
__device__ int   g_rowend[N_NODES];
__device__ int   g_cursor[N_NODES];
__device__ int   g_total;
__device__ int   g_esrc[N_EDGES];
__device__ float g_enrm[N_EDGES];

// split activation buffers (two sets for MLP ping-pong)
__device__ __nv_bfloat16 g_Ahi0[ASZ], g_Alo0[ASZ];
__device__ __nv_bfloat16 g_Ahi1[ASZ], g_Alo1[ASZ];
// split weights: w0 @0 (320x256), then 5 x 256x256
#define WSZ (KPAD0*EMB + 5*EMB*EMB)
__device__ __nv_bfloat16 g_Whi[WSZ], g_Wlo[WSZ];

template<int S> __device__ __forceinline__ __nv_bfloat16* ahi() { return S ? g_Ahi1 : g_Ahi0; }
template<int S> __device__ __forceinline__ __nv_bfloat16* alo() { return S ? g_Alo1 : g_Alo0; }

// ---------------- CSR build (order-free, no scan) ----------------
__global__ void k_zero() {
    int i = blockIdx.x * blockDim.x + threadIdx.x;
    if (i < N_NODES) g_cnt[i] = 0;
    if (i == 0) g_total = 0;
}
__global__ void k_hist(const int* __restrict__ dst) {
    int e = blockIdx.x * blockDim.x + threadIdx.x;
    if (e < N_EDGES) atomicAdd(&g_cnt[dst[e]], 1);
}
__global__ void k_dinv_k() {
    int i = blockIdx.x * blockDim.x + threadIdx.x;
    if (i < N_NODES) g_dinv[i] = rsqrtf(1.0f + (float)g_cnt[i]);
}
__global__ void k_offsets() {
    int i = blockIdx.x * blockDim.x + threadIdx.x;
    if (i < N_NODES) {
        int c = g_cnt[i];
        int st = atomicAdd(&g_total, c);
        g_rowstart[i] = st;
        g_rowend[i] = st + c;
        g_cursor[i] = st;
    }
}
__global__ void k_fill(const int* __restrict__ src, const int* __restrict__ dst) {
    int e = blockIdx.x * blockDim.x + threadIdx.x;
    if (e >= N_EDGES) return;
    int s = src[e], d = dst[e];
    int pos = atomicAdd(&g_cursor[d], 1);
    g_esrc[pos] = s;
    g_enrm[pos] = g_dinv[s] * g_dinv[d];
}

// ---------------- split precompute ----------------
__device__ __forceinline__ void split_write(__nv_bfloat16* hi, __nv_bfloat16* lo,
                                            size_t idx, float v) {
    __nv_bfloat16 h = __float2bfloat16(v);
    hi[idx] = h;
    lo[idx] = __float2bfloat16(v - __bfloat162float(h));
}

// x [20000,300] -> set0 with row stride 320, zero padded
__global__ void k_split_x(const float* __restrict__ x) {
    long long idx = (long long)blockIdx.x * blockDim.x + threadIdx.x;
    if (idx >= (long long)N_NODES * KPAD0) return;
    int row = (int)(idx / KPAD0);
    int k = (int)(idx % KPAD0);
    float v = (k < 300) ? x[(size_t)row * 300 + k] : 0.0f;
    split_write(g_Ahi0, g_Alo0, (size_t)idx, v);
}

// weight [K,256] -> g_W at off, padded to Kpad rows
__global__ void k_split_w(const float* __restrict__ w, int K, int Kpad, int off) {
    int idx = blockIdx.x * blockDim.x + threadIdx.x;
    if (idx >= Kpad * EMB) return;
    int kr = idx / EMB;
    int c = idx % EMB;
    float v = (kr < K) ? w[(size_t)kr * EMB + c] : 0.0f;
    split_write(g_Whi, g_Wlo, (size_t)off + idx, v);
}

// ---------------- bf16-split tensor GEMM ----------------
// C[M,256] = A[M,Kpad] @ W[Kpad,256], A/W pre-split bf16.
// OUT: 0 = float g_bufA (direct store for full tiles), 1 = float ext,
//      2 = split->set0, 3 = split->set1
template<int ASEL, int OUT, bool BIAS, bool RELU>
__global__ __launch_bounds__(256) void gemm_bf16(
    const float* __restrict__ bias, float* __restrict__ Cext,
    int M, int Kpad, int woff)
{
    const __nv_bfloat16* Ah = ahi<ASEL>();
    const __nv_bfloat16* Al = alo<ASEL>();

    __shared__ __nv_bfloat16 As_hi[128][40];
    __shared__ __nv_bfloat16 As_lo[128][40];
    __shared__ __nv_bfloat16 Ws_hi[32][136];
    __shared__ __nv_bfloat16 Ws_lo[32][136];
    __shared__ float stage[8][16][20];

    const int tid  = threadIdx.x;
    const int warp = tid >> 5;
    const int lane = tid & 31;
    const int warpM = warp >> 2;        // 0..1
    const int warpN = warp & 3;         // 0..3
    const int rowBase = blockIdx.y * 128;
    const int colBase = blockIdx.x * 128;

    wmma::fragment<wmma::accumulator, 16, 16, 16, float> acc[4][2];
    #pragma unroll
    for (int i = 0; i < 4; i++)
        #pragma unroll
        for (int j = 0; j < 2; j++) wmma::fill_fragment(acc[i][j], 0.0f);

    for (int k0 = 0; k0 < Kpad; k0 += 32) {
        // A slab: 128 rows x 32 k, uint4 (8 bf16) per load, 2 per thread
        #pragma unroll
        for (int it = 0; it < 2; it++) {
            int r = (tid >> 2) + it * 64;
            int cc = (tid & 3) * 8;
            size_t g = (size_t)(rowBase + r) * Kpad + k0 + cc;
            *reinterpret_cast<uint4*>(&As_hi[r][cc]) = *reinterpret_cast<const uint4*>(&Ah[g]);
            *reinterpret_cast<uint4*>(&As_lo[r][cc]) = *reinterpret_cast<const uint4*>(&Al[g]);
        }
        // W slab: 32 rows x 128 cols
        #pragma unroll
        for (int it = 0; it < 2; it++) {
            int linear = tid + it * 256;
            int kr = linear >> 4;
            int c8 = (linear & 15) * 8;
            size_t g = (size_t)woff + (size_t)(k0 + kr) * EMB + colBase + c8;
            *reinterpret_cast<uint4*>(&Ws_hi[kr][c8]) = *reinterpret_cast<const uint4*>(&g_Whi[g]);
            *reinterpret_cast<uint4*>(&Ws_lo[kr][c8]) = *reinterpret_cast<const uint4*>(&g_Wlo[g]);
        }
        __syncthreads();

        #pragma unroll
        for (int kk = 0; kk < 32; kk += 16) {
            wmma::fragment<wmma::matrix_a, 16, 16, 16, __nv_bfloat16, wmma::row_major> a_hi[4], a_lo[4];
            wmma::fragment<wmma::matrix_b, 16, 16, 16, __nv_bfloat16, wmma::row_major> b_hi[2], b_lo[2];
            #pragma unroll
            for (int i = 0; i < 4; i++) {
                int m = warpM * 64 + i * 16;
                wmma::load_matrix_sync(a_hi[i], &As_hi[m][kk], 40);
                wmma::load_matrix_sync(a_lo[i], &As_lo[m][kk], 40);
            }
            #pragma unroll
            for (int j = 0; j < 2; j++) {
                int n = warpN * 32 + j * 16;
                wmma::load_matrix_sync(b_hi[j], &Ws_hi[kk][n], 136);
                wmma::load_matrix_sync(b_lo[j], &Ws_lo[kk][n], 136);
            }
            #pragma unroll
            for (int i = 0; i < 4; i++)
                #pragma unroll
                for (int j = 0; j < 2; j++) {
                    wmma::mma_sync(acc[i][j], a_hi[i], b_hi[j], acc[i][j]);
                    wmma::mma_sync(acc[i][j], a_hi[i], b_lo[j], acc[i][j]);
                    wmma::mma_sync(acc[i][j], a_lo[i], b_hi[j], acc[i][j]);
                }
        }
        __syncthreads();
    }

    // ---- epilogue
    float* Cf = (OUT == 0) ? g_bufA : Cext;
    __nv_bfloat16* Ohi = (OUT == 2) ? g_Ahi0 : g_Ahi1;
    __nv_bfloat16* Olo = (OUT == 2) ? g_Alo0 : g_Alo1;

    #pragma unroll
    for (int i = 0; i < 4; i++) {
        #pragma unroll
        for (int j = 0; j < 2; j++) {
            int gRow0 = rowBase + warpM * 64 + i * 16;
            int gCol0 = colBase + warpN * 32 + j * 16;
            if (OUT <= 1 && !BIAS && !RELU && gRow0 + 16 <= M) {
                wmma::store_matrix_sync(&Cf[(size_t)gRow0 * EMB + gCol0], acc[i][j],
                                        EMB, wmma::mem_row_major);
            } else {
                wmma::store_matrix_sync(&stage[warp][0][0], acc[i][j], 20, wmma::mem_row_major);
                __syncwarp();
                int r = lane >> 1;
                int cs = (lane & 1) * 8;
                int gRow = gRow0 + r;
                if (gRow < M) {
                    #pragma unroll
                    for (int u = 0; u < 8; u++) {
                        float v = stage[warp][r][cs + u];
                        int gCol = gCol0 + cs + u;
                        if (BIAS) v += bias[gCol];
                        if (RELU) v = fmaxf(v, 0.0f);
                        if (OUT >= 2) {
                            split_write(Ohi, Olo, (size_t)gRow * EMB + gCol, v);
                        } else {
                            Cf[(size_t)gRow * EMB + gCol] = v;
                        }
                    }
                }
                __syncwarp();
            }
        }
    }
}

// ---------------- fused CSR aggregation -> split set0 ----------------
// reads g_bufA (conv GEMM output); 4 nodes/block, 64 threads x float4 per node
template<bool RELU>
__global__ __launch_bounds__(256) void k_agg_csr(const float* __restrict__ bias) {
    int d = blockIdx.x * 4 + (threadIdx.x >> 6);
    int c = (threadIdx.x & 63) * 4;
    if (d >= N_NODES) return;

    float di = g_dinv[d];
    float w = di * di;
    float4 acc = *reinterpret_cast<const float4*>(&g_bufA[(size_t)d * EMB + c]);
    float4 bs  = *reinterpret_cast<const float4*>(&bias[c]);
    acc.x = acc.x * w + bs.x;
    acc.y = acc.y * w + bs.y;
    acc.z = acc.z * w + bs.z;
    acc.w = acc.w * w + bs.w;

    int b0 = g_rowstart[d];
    int b1 = g_rowend[d];
    for (int j = b0; j < b1; j++) {
        int s = g_esrc[j];
        float nrm = g_enrm[j];
        float4 v = *reinterpret_cast<const float4*>(&g_bufA[(size_t)s * EMB + c]);
        acc.x = fmaf(v.x, nrm, acc.x);
        acc.y = fmaf(v.y, nrm, acc.y);
        acc.z = fmaf(v.z, nrm, acc.z);
        acc.w = fmaf(v.w, nrm, acc.w);
    }
    if (RELU) {
        acc.x = fmaxf(acc.x, 0.f); acc.y = fmaxf(acc.y, 0.f);
        acc.z = fmaxf(acc.z, 0.f); acc.w = fmaxf(acc.w, 0.f);
    }
    size_t base = (size_t)d * EMB + c;
    split_write(g_Ahi0, g_Alo0, base + 0, acc.x);
    split_write(g_Ahi0, g_Alo0, base + 1, acc.y);
    split_write(g_Ahi0, g_Alo0, base + 2, acc.z);
    split_write(g_Ahi0, g_Alo0, base + 3, acc.w);
}

// ---------------- launch ----------------
extern "C" void kernel_launch(void* const* d_in, const int* in_sizes, int n_in,
                              void* d_out, int out_size) {
    const float* x       = (const float*)d_in[0];
    const int*   ei      = (const int*)d_in[1];     // [2, E] int32
    const float* conv0_w = (const float*)d_in[2];
    const float* conv0_b = (const float*)d_in[3];
    const float* conv1_w = (const float*)d_in[4];
    const float* conv1_b = (const float*)d_in[5];
    const float* conv2_w = (const float*)d_in[6];
    const float* conv2_b = (const float*)d_in[7];
    const float* mlp1_w  = (const float*)d_in[8];
    const float* mlp1_b  = (const float*)d_in[9];
    const float* mlp2_w  = (const float*)d_in[10];
    const float* mlp2_b  = (const float*)d_in[11];
    const float* mlp3_w  = (const float*)d_in[12];
    const float* mlp3_b  = (const float*)d_in[13];
    float* out = (float*)d_out;

    const int* src = ei;
    const int* dst = ei + N_EDGES;

    // CSR build + norms (scan-free)
    k_zero<<<(N_NODES + 255) / 256, 256>>>();
    k_hist<<<(N_EDGES + 255) / 256, 256>>>(dst);
    k_dinv_k<<<(N_NODES + 255) / 256, 256>>>();
    k_offsets<<<(N_NODES + 255) / 256, 256>>>();
    k_fill<<<(N_EDGES + 255) / 256, 256>>>(src, dst);

    // pre-split x and all weights
    k_split_x<<<(int)(((long long)N_NODES * KPAD0 + 255) / 256), 256>>>(x);
    const int W0 = 0;
    const int W1 = KPAD0 * EMB;
    const int W2 = W1 + EMB * EMB;
    const int W3 = W2 + EMB * EMB;
    const int W4 = W3 + EMB * EMB;
    const int W5 = W4 + EMB * EMB;
    k_split_w<<<(KPAD0 * EMB + 255) / 256, 256>>>(conv0_w, 300, KPAD0, W0);
    k_split_w<<<(EMB * EMB + 255) / 256, 256>>>(conv1_w, EMB, EMB, W1);
    k_split_w<<<(EMB * EMB + 255) / 256, 256>>>(conv2_w, EMB, EMB, W2);
    k_split_w<<<(EMB * EMB + 255) / 256, 256>>>(mlp1_w, EMB, EMB, W3);
    k_split_w<<<(EMB * EMB + 255) / 256, 256>>>(mlp2_w, EMB, EMB, W4);
    k_split_w<<<(EMB * EMB + 255) / 256, 256>>>(mlp3_w, EMB, EMB, W5);

    dim3 gblk(256);
    dim3 ggrid(2, (N_NODES + 127) / 128);   // (2, 157)
    const int aggBlocks = (N_NODES + 3) / 4;

    // conv0: bufA = A0 @ W0 ; set0 = agg(bufA)+b0, relu
    gemm_bf16<0, 0, false, false><<<ggrid, gblk>>>(conv0_b, out, N_NODES, KPAD0, W0);
    k_agg_csr<true ><<<aggBlocks, 256>>>(conv0_b);
    // conv1
    gemm_bf16<0, 0, false, false><<<ggrid, gblk>>>(conv1_b, out, N_NODES, EMB, W1);
    k_agg_csr<true ><<<aggBlocks, 256>>>(conv1_b);
    // conv2 (no relu)
    gemm_bf16<0, 0, false, false><<<ggrid, gblk>>>(conv2_b, out, N_NODES, EMB, W2);
    k_agg_csr<false><<<aggBlocks, 256>>>(conv2_b);

    // MLP: set0 -> set1 -> set0 -> out
    gemm_bf16<0, 3, true, true ><<<ggrid, gblk>>>(mlp1_b, out, N_NODES, EMB, W3);
    gemm_bf16<1, 2, true, true ><<<ggrid, gblk>>>(mlp2_b, out, N_NODES, EMB, W4);
    gemm_bf16<0, 1, true, false><<<ggrid, gblk>>>(mlp3_b, out, N_NODES, EMB, W5);
}

// round 13
// speedup vs baseline: 3.7357x; 1.1233x over previous
#include <cuda_runtime.h>
#include <cuda_bf16.h>
#include <mma.h>
#include <math.h>

using namespace nvcuda;

#define N_NODES 20000
#define N_EDGES 320000
#define EMB 256
#define KPAD0 320              // conv0 K=300 padded; others use 256
#define MROWS 20096            // 157*128 rows (OOB-read safe)
#define ASZ (MROWS * KPAD0)

// ---------------- device-global scratch ----------------
__device__ float g_bufA[N_NODES * EMB];          // conv GEMM float output
__device__ float g_dinv[N_NODES];
__device__ int   g_cnt[N_NODES];
__device__ int   g_rowstart[N_NODES];
__device__ int   g_rowend[N_NODES];
__device__ int   g_cursor[N_NODES];
__device__ int   g_total;
__device__ int   g_esrc[N_EDGES];
__device__ float g_enrm[N_EDGES];

// split activation buffers (two sets for ping-pong)
__device__ __nv_bfloat16 g_Ahi0[ASZ], g_Alo0[ASZ];
__device__ __nv_bfloat16 g_Ahi1[ASZ], g_Alo1[ASZ];
// split weights: w0 @0 (320x256), then 5 x 256x256
#define WSZ (KPAD0*EMB + 5*EMB*EMB)
__device__ __nv_bfloat16 g_Whi[WSZ], g_Wlo[WSZ];

template<int S> __device__ __forceinline__ __nv_bfloat16* ahi() { return S ? g_Ahi1 : g_Ahi0; }
template<int S> __device__ __forceinline__ __nv_bfloat16* alo() { return S ? g_Alo1 : g_Alo0; }

// ---------------- cp.async helpers ----------------
__device__ __forceinline__ void cp16(void* smem_dst, const void* gsrc) {
    unsigned sa = (unsigned)__cvta_generic_to_shared(smem_dst);
    asm volatile("cp.async.cg.shared.global [%0], [%1], 16;\n" :: "r"(sa), "l"(gsrc));
}
__device__ __forceinline__ void cp_commit() {
    asm volatile("cp.async.commit_group;\n" ::: "memory");
}
template<int N>
__device__ __forceinline__ void cp_wait() {
    asm volatile("cp.async.wait_group %0;\n" :: "n"(N) : "memory");
}

// ---------------- CSR build (order-free, no scan) ----------------
__global__ void k_zero() {
    int i = blockIdx.x * blockDim.x + threadIdx.x;
    if (i < N_NODES) g_cnt[i] = 0;
    if (i == 0) g_total = 0;
}
__global__ void k_hist(const int* __restrict__ dst) {
    int e = blockIdx.x * blockDim.x + threadIdx.x;
    if (e < N_EDGES) atomicAdd(&g_cnt[dst[e]], 1);
}
__global__ void k_node_setup() {   // dinv + segment offsets
    int i = blockIdx.x * blockDim.x + threadIdx.x;
    if (i < N_NODES) {
        int c = g_cnt[i];
        g_dinv[i] = rsqrtf(1.0f + (float)c);
        int st = atomicAdd(&g_total, c);
        g_rowstart[i] = st;
        g_rowend[i] = st + c;
        g_cursor[i] = st;
    }
}
__global__ void k_fill(const int* __restrict__ src, const int* __restrict__ dst) {
    int e = blockIdx.x * blockDim.x + threadIdx.x;
    if (e >= N_EDGES) return;
    int s = src[e], d = dst[e];
    int pos = atomicAdd(&g_cursor[d], 1);
    g_esrc[pos] = s;
    g_enrm[pos] = g_dinv[s] * g_dinv[d];
}

// ---------------- split precompute ----------------
__device__ __forceinline__ void split_write(__nv_bfloat16* hi, __nv_bfloat16* lo,
                                            size_t idx, float v) {
    __nv_bfloat16 h = __float2bfloat16(v);
    hi[idx] = h;
    lo[idx] = __float2bfloat16(v - __bfloat162float(h));
}

// x [20000,300] -> set0 with row stride 320, zero padded, float4 chunks
__global__ void k_split_x(const float* __restrict__ x) {
    int idx = blockIdx.x * blockDim.x + threadIdx.x;   // chunk id
    const int CH_PER_ROW = KPAD0 / 4;                  // 80
    if (idx >= N_NODES * CH_PER_ROW) return;
    int row = idx / CH_PER_ROW;
    int k = (idx % CH_PER_ROW) * 4;
    float4 v = make_float4(0.f, 0.f, 0.f, 0.f);
    if (k < 300) {
        if (k + 3 < 300) v = *reinterpret_cast<const float4*>(&x[(size_t)row * 300 + k]);
        else {
            float t[4] = {0.f, 0.f, 0.f, 0.f};
            for (int u = 0; u < 4; u++) if (k + u < 300) t[u] = x[(size_t)row * 300 + k + u];
            v = make_float4(t[0], t[1], t[2], t[3]);
        }
    }
    size_t base = (size_t)row * KPAD0 + k;
    split_write(g_Ahi0, g_Alo0, base + 0, v.x);
    split_write(g_Ahi0, g_Alo0, base + 1, v.y);
    split_write(g_Ahi0, g_Alo0, base + 2, v.z);
    split_write(g_Ahi0, g_Alo0, base + 3, v.w);
}

// weight [K,256] -> g_W at off, padded to Kpad rows
__global__ void k_split_w(const float* __restrict__ w, int K, int Kpad, int off) {
    int idx = blockIdx.x * blockDim.x + threadIdx.x;
    if (idx >= Kpad * EMB) return;
    int kr = idx / EMB;
    int c = idx % EMB;
    float v = (kr < K) ? w[(size_t)kr * EMB + c] : 0.0f;
    split_write(g_Whi, g_Wlo, (size_t)off + idx, v);
}

// ---------------- bf16-split tensor GEMM, 2-stage cp.async pipeline ----------------
// C[M,256] = A[M,Kpad] @ W[Kpad,256].  OUT: 0=g_bufA float, 1=float ext,
// 2=split->set0, 3=split->set1
#define AST 40     // A smem row stride (elements)
#define WST 136    // W smem row stride
// dynamic smem layout (bf16 elements unless noted)
#define OFF_AH 0
#define OFF_AL (2 * 128 * AST)
#define OFF_WH (OFF_AL + 2 * 128 * AST)
#define OFF_WL (OFF_WH + 2 * 32 * WST)
#define OFF_ST (OFF_WL + 2 * 32 * WST)              // float stage, 8*16*20
#define SMEM_ELE (OFF_ST)
#define SMEM_BYTES (SMEM_ELE * 2 + 8 * 16 * 20 * 4)

template<int ASEL, int OUT, bool BIAS, bool RELU>
__global__ __launch_bounds__(256, 2) void gemm_bf16(
    const float* __restrict__ bias, float* __restrict__ Cext,
    int M, int Kpad, int woff)
{
    extern __shared__ __nv_bfloat16 smem[];
    __nv_bfloat16* Ash = smem + OFF_AH;
    __nv_bfloat16* Asl = smem + OFF_AL;
    __nv_bfloat16* Wsh = smem + OFF_WH;
    __nv_bfloat16* Wsl = smem + OFF_WL;
    float* stage = reinterpret_cast<float*>(smem + OFF_ST);

    const __nv_bfloat16* Ah = ahi<ASEL>();
    const __nv_bfloat16* Al = alo<ASEL>();

    const int tid  = threadIdx.x;
    const int warp = tid >> 5;
    const int lane = tid & 31;
    const int warpM = warp >> 2;        // 0..1
    const int warpN = warp & 3;         // 0..3
    const int rowBase = blockIdx.y * 128;
    const int colBase = blockIdx.x * 128;

    wmma::fragment<wmma::accumulator, 16, 16, 16, float> acc[4][2];
    #pragma unroll
    for (int i = 0; i < 4; i++)
        #pragma unroll
        for (int j = 0; j < 2; j++) wmma::fill_fragment(acc[i][j], 0.0f);

    // stage loader: 8 x 16B cp.async per thread
    auto load_stage = [&](int st, int k0) {
        __nv_bfloat16* ah = Ash + st * 128 * AST;
        __nv_bfloat16* al = Asl + st * 128 * AST;
        __nv_bfloat16* wh = Wsh + st * 32 * WST;
        __nv_bfloat16* wl = Wsl + st * 32 * WST;
        #pragma unroll
        for (int it = 0; it < 2; it++) {
            int slot = tid + it * 256;          // 0..511
            int r = slot >> 2;
            int cc = (slot & 3) * 8;
            size_t g = (size_t)(rowBase + r) * Kpad + k0 + cc;
            cp16(&ah[r * AST + cc], &Ah[g]);
            cp16(&al[r * AST + cc], &Al[g]);
        }
        #pragma unroll
        for (int it = 0; it < 2; it++) {
            int slot = tid + it * 256;          // 0..511
            int kr = slot >> 4;
            int c8 = (slot & 15) * 8;
            size_t g = (size_t)woff + (size_t)(k0 + kr) * EMB + colBase + c8;
            cp16(&wh[kr * WST + c8], &g_Whi[g]);
            cp16(&wl[kr * WST + c8], &g_Wlo[g]);
        }
    };

    const int nK = Kpad >> 5;
    load_stage(0, 0);
    cp_commit();

    for (int ks = 0; ks < nK; ks++) {
        if (ks + 1 < nK) {
            load_stage((ks + 1) & 1, (ks + 1) << 5);
            cp_commit();
            cp_wait<1>();
        } else {
            cp_wait<0>();
        }
        __syncthreads();

        int st = ks & 1;
        const __nv_bfloat16* ah = Ash + st * 128 * AST;
        const __nv_bfloat16* al = Asl + st * 128 * AST;
        const __nv_bfloat16* wh = Wsh + st * 32 * WST;
        const __nv_bfloat16* wl = Wsl + st * 32 * WST;

        #pragma unroll
        for (int kk = 0; kk < 32; kk += 16) {
            wmma::fragment<wmma::matrix_a, 16, 16, 16, __nv_bfloat16, wmma::row_major> a_hi[4], a_lo[4];
            wmma::fragment<wmma::matrix_b, 16, 16, 16, __nv_bfloat16, wmma::row_major> b_hi[2], b_lo[2];
            #pragma unroll
            for (int i = 0; i < 4; i++) {
                int m = warpM * 64 + i * 16;
                wmma::load_matrix_sync(a_hi[i], &ah[m * AST + kk], AST);
                wmma::load_matrix_sync(a_lo[i], &al[m * AST + kk], AST);
            }
            #pragma unroll
            for (int j = 0; j < 2; j++) {
                int n = warpN * 32 + j * 16;
                wmma::load_matrix_sync(b_hi[j], &wh[kk * WST + n], WST);
                wmma::load_matrix_sync(b_lo[j], &wl[kk * WST + n], WST);
            }
            #pragma unroll
            for (int i = 0; i < 4; i++)
                #pragma unroll
                for (int j = 0; j < 2; j++) {
                    wmma::mma_sync(acc[i][j], a_hi[i], b_hi[j], acc[i][j]);
                    wmma::mma_sync(acc[i][j], a_hi[i], b_lo[j], acc[i][j]);
                    wmma::mma_sync(acc[i][j], a_lo[i], b_hi[j], acc[i][j]);
                }
        }
        __syncthreads();
    }

    // ---- epilogue
    float* Cf = (OUT == 0) ? g_bufA : Cext;
    __nv_bfloat16* Ohi = (OUT == 2) ? g_Ahi0 : g_Ahi1;
    __nv_bfloat16* Olo = (OUT == 2) ? g_Alo0 : g_Alo1;
    float* mystage = stage + warp * 16 * 20;

    #pragma unroll
    for (int i = 0; i < 4; i++) {
        #pragma unroll
        for (int j = 0; j < 2; j++) {
            int gRow0 = rowBase + warpM * 64 + i * 16;
            int gCol0 = colBase + warpN * 32 + j * 16;
            if (OUT <= 1 && !BIAS && !RELU && gRow0 + 16 <= M) {
                wmma::store_matrix_sync(&Cf[(size_t)gRow0 * EMB + gCol0], acc[i][j],
                                        EMB, wmma::mem_row_major);
            } else {
                wmma::store_matrix_sync(mystage, acc[i][j], 20, wmma::mem_row_major);
                __syncwarp();
                int r = lane >> 1;
                int cs = (lane & 1) * 8;
                int gRow = gRow0 + r;
                if (gRow < M) {
                    #pragma unroll
                    for (int u = 0; u < 8; u++) {
                        float v = mystage[r * 20 + cs + u];
                        int gCol = gCol0 + cs + u;
                        if (BIAS) v += bias[gCol];
                        if (RELU) v = fmaxf(v, 0.0f);
                        if (OUT >= 2) {
                            split_write(Ohi, Olo, (size_t)gRow * EMB + gCol, v);
                        } else {
                            Cf[(size_t)gRow * EMB + gCol] = v;
                        }
                    }
                }
                __syncwarp();
            }
        }
    }
}

// ---------------- fused CSR aggregation -> split set0 ----------------
template<bool RELU>
__global__ __launch_bounds__(256) void k_agg_csr(const float* __restrict__ bias) {
    int d = blockIdx.x * 4 + (threadIdx.x >> 6);
    int c = (threadIdx.x & 63) * 4;
    if (d >= N_NODES) return;

    float di = g_dinv[d];
    float w = di * di;
    float4 acc = *reinterpret_cast<const float4*>(&g_bufA[(size_t)d * EMB + c]);
    float4 bs  = *reinterpret_cast<const float4*>(&bias[c]);
    acc.x = acc.x * w + bs.x;
    acc.y = acc.y * w + bs.y;
    acc.z = acc.z * w + bs.z;
    acc.w = acc.w * w + bs.w;

    int b0 = g_rowstart[d];
    int b1 = g_rowend[d];
    for (int j = b0; j < b1; j++) {
        int s = g_esrc[j];
        float nrm = g_enrm[j];
        float4 v = *reinterpret_cast<const float4*>(&g_bufA[(size_t)s * EMB + c]);
        acc.x = fmaf(v.x, nrm, acc.x);
        acc.y = fmaf(v.y, nrm, acc.y);
        acc.z = fmaf(v.z, nrm, acc.z);
        acc.w = fmaf(v.w, nrm, acc.w);
    }
    if (RELU) {
        acc.x = fmaxf(acc.x, 0.f); acc.y = fmaxf(acc.y, 0.f);
        acc.z = fmaxf(acc.z, 0.f); acc.w = fmaxf(acc.w, 0.f);
    }
    size_t base = (size_t)d * EMB + c;
    split_write(g_Ahi0, g_Alo0, base + 0, acc.x);
    split_write(g_Ahi0, g_Alo0, base + 1, acc.y);
    split_write(g_Ahi0, g_Alo0, base + 2, acc.z);
    split_write(g_Ahi0, g_Alo0, base + 3, acc.w);
}

// ---------------- launch ----------------
extern "C" void kernel_launch(void* const* d_in, const int* in_sizes, int n_in,
                              void* d_out, int out_size) {
    const float* x       = (const float*)d_in[0];
    const int*   ei      = (const int*)d_in[1];     // [2, E] int32
    const float* conv0_w = (const float*)d_in[2];
    const float* conv0_b = (const float*)d_in[3];
    const float* conv1_w = (const float*)d_in[4];
    const float* conv1_b = (const float*)d_in[5];
    const float* conv2_w = (const float*)d_in[6];
    const float* conv2_b = (const float*)d_in[7];
    const float* mlp1_w  = (const float*)d_in[8];
    const float* mlp1_b  = (const float*)d_in[9];
    const float* mlp2_w  = (const float*)d_in[10];
    const float* mlp2_b  = (const float*)d_in[11];
    const float* mlp3_w  = (const float*)d_in[12];
    const float* mlp3_b  = (const float*)d_in[13];
    float* out = (float*)d_out;

    const int* src = ei;
    const int* dst = ei + N_EDGES;

    // raise dynamic smem limit (idempotent; not a stream op)
    static bool attr_done = false;
    if (!attr_done) {
        cudaFuncSetAttribute(gemm_bf16<0, 0, false, false>, cudaFuncAttributeMaxDynamicSharedMemorySize, SMEM_BYTES);
        cudaFuncSetAttribute(gemm_bf16<0, 3, true,  true >, cudaFuncAttributeMaxDynamicSharedMemorySize, SMEM_BYTES);
        cudaFuncSetAttribute(gemm_bf16<1, 2, true,  true >, cudaFuncAttributeMaxDynamicSharedMemorySize, SMEM_BYTES);
        cudaFuncSetAttribute(gemm_bf16<0, 1, true,  false>, cudaFuncAttributeMaxDynamicSharedMemorySize, SMEM_BYTES);
        attr_done = true;
    }

    // CSR build + norms
    k_zero<<<(N_NODES + 255) / 256, 256>>>();
    k_hist<<<(N_EDGES + 255) / 256, 256>>>(dst);
    k_node_setup<<<(N_NODES + 255) / 256, 256>>>();
    k_fill<<<(N_EDGES + 255) / 256, 256>>>(src, dst);

    // pre-split x and all weights
    k_split_x<<<(N_NODES * (KPAD0 / 4) + 255) / 256, 256>>>(x);
    const int W0 = 0;
    const int W1 = KPAD0 * EMB;
    const int W2 = W1 + EMB * EMB;
    const int W3 = W2 + EMB * EMB;
    const int W4 = W3 + EMB * EMB;
    const int W5 = W4 + EMB * EMB;
    k_split_w<<<(KPAD0 * EMB + 255) / 256, 256>>>(conv0_w, 300, KPAD0, W0);
    k_split_w<<<(EMB * EMB + 255) / 256, 256>>>(conv1_w, EMB, EMB, W1);
    k_split_w<<<(EMB * EMB + 255) / 256, 256>>>(conv2_w, EMB, EMB, W2);
    k_split_w<<<(EMB * EMB + 255) / 256, 256>>>(mlp1_w, EMB, EMB, W3);
    k_split_w<<<(EMB * EMB + 255) / 256, 256>>>(mlp2_w, EMB, EMB, W4);
    k_split_w<<<(EMB * EMB + 255) / 256, 256>>>(mlp3_w, EMB, EMB, W5);

    dim3 gblk(256);
    dim3 ggrid(2, (N_NODES + 127) / 128);   // (2, 157)
    const int aggBlocks = (N_NODES + 3) / 4;

    // conv0
    gemm_bf16<0, 0, false, false><<<ggrid, gblk, SMEM_BYTES>>>(conv0_b, out, N_NODES, KPAD0, W0);
    k_agg_csr<true ><<<aggBlocks, 256>>>(conv0_b);
    // conv1
    gemm_bf16<0, 0, false, false><<<ggrid, gblk, SMEM_BYTES>>>(conv1_b, out, N_NODES, EMB, W1);
    k_agg_csr<true ><<<aggBlocks, 256>>>(conv1_b);
    // conv2 (no relu)
    gemm_bf16<0, 0, false, false><<<ggrid, gblk, SMEM_BYTES>>>(conv2_b, out, N_NODES, EMB, W2);
    k_agg_csr<false><<<aggBlocks, 256>>>(conv2_b);

    // MLP: set0 -> set1 -> set0 -> out
    gemm_bf16<0, 3, true, true ><<<ggrid, gblk, SMEM_BYTES>>>(mlp1_b, out, N_NODES, EMB, W3);
    gemm_bf16<1, 2, true, true ><<<ggrid, gblk, SMEM_BYTES>>>(mlp2_b, out, N_NODES, EMB, W4);
    gemm_bf16<0, 1, true, false><<<ggrid, gblk, SMEM_BYTES>>>(mlp3_b, out, N_NODES, EMB, W5);
}